// round 4
// baseline (speedup 1.0000x reference)
#include <cuda_runtime.h>
#include <math.h>
#include <stdint.h>

// ---------------- problem constants ----------------
#define Nn 262144
#define Dd 64
#define Kk 64
#define NB 72            // MMA N: 64 clusters + 1 background col + 7 pad
#define TM 128           // rows per CTA
#define NTILES (Nn/TM)   // 2048
#define TPB 256
#define LOG2PI_F 1.83787706640934548356f
#define PLV0 (-2.0f)

// ---------------- device globals (no allocs allowed) ----------------
__device__ float  g_Bmat[NB*128];   // [n][k]: k<64 -> -2*mu*a ; k>=64 -> a (col 64 = bg wts)
__device__ float  g_offs[Kk];
__device__ float  g_logpi[Kk];
__device__ float  g_C0;
__device__ double g_kl;
__device__ double g_lse;
__device__ unsigned int g_count;

__device__ __forceinline__ float tf32r(float x) {
    float r; asm("cvt.rna.tf32.f32 %0, %1;" : "=f"(r) : "f"(x)); return r;
}

__device__ __forceinline__ void mma8(float c[4],
                                     uint32_t a0, uint32_t a1, uint32_t a2, uint32_t a3,
                                     uint32_t b0, uint32_t b1) {
    asm volatile("mma.sync.aligned.m16n8k8.row.col.f32.tf32.tf32.f32 "
        "{%0,%1,%2,%3}, {%4,%5,%6,%7}, {%8,%9}, {%0,%1,%2,%3};"
        : "+f"(c[0]), "+f"(c[1]), "+f"(c[2]), "+f"(c[3])
        : "r"(a0), "r"(a1), "r"(a2), "r"(a3), "r"(b0), "r"(b1));
}

// ---------------------------------------------------------------------------
// Kernel 1: precompute (1 block x 1024 threads), fast-math, parallel reductions.
// ---------------------------------------------------------------------------
__global__ void precompute_kernel(const float* __restrict__ u_noise,
                                  const float* __restrict__ phi_logits,
                                  const float* __restrict__ q_mu,
                                  const float* __restrict__ q_logvar,
                                  const float* __restrict__ pi_logits,
                                  const float* __restrict__ prior_p,
                                  float* __restrict__ out)
{
    __shared__ float phi_s[64], red[64], red2[64], pil_s[64], ex_s[64];
    __shared__ float obuf[Kk*Dd];
    int t = threadIdx.x;

    if (t < 64) {
        float uu  = u_noise[t];
        float g   = -__logf(-__logf(uu + 1e-9f) + 1e-9f);
        float pl  = phi_logits[t];
        float phi = 1.0f / (1.0f + __expf(-(pl + g)));
        phi_s[t]  = phi;
        float qphi = 1.0f / (1.0f + __expf(-pl));
        qphi = fminf(fmaxf(qphi, 1e-6f), 1.0f - 1e-6f);
        out[1 + t] = qphi;
        float p = fminf(fmaxf(prior_p[t], 1e-6f), 1.0f - 1e-6f);
        // KL term: use accurate logf here (cheap, only 64 threads, feeds scalar)
        red[t]  = qphi * (__logf(qphi) - __logf(p))
                + (1.0f - qphi) * (__logf(1.0f - qphi) - __logf(1.0f - p));
        red2[t] = (1.0f - phi) * (LOG2PI_F + PLV0);
        pil_s[t] = pi_logits[t];
    }
    __syncthreads();
    // parallel reductions for kl / C0 (2 warps worth of data)
    if (t < 64) {
        float a = red[t], b = red2[t];
        #pragma unroll
        for (int s = 16; s; s >>= 1) {
            a += __shfl_xor_sync(0xffffffffu, a, s);
            b += __shfl_xor_sync(0xffffffffu, b, s);
        }
        if ((t & 31) == 0) { red[t >> 5] = a; red2[t >> 5] = b; }
    }
    __syncthreads();
    if (t == 0) {
        g_kl  = (double)(red[0] + red[1]) * (double)Nn;
        g_C0  = red2[0] + red2[1];
        g_lse = 0.0;
        g_count = 0u;
    }
    // log softmax(pi)+1e-9: parallel max/sum via the ex_s buffer
    if (t < 64) {
        float m = pil_s[t];
        #pragma unroll
        for (int s = 16; s; s >>= 1) m = fmaxf(m, __shfl_xor_sync(0xffffffffu, m, s));
        if ((t & 31) == 0) ex_s[t >> 5] = m;
    }
    __syncthreads();
    if (t < 64) {
        float m = fmaxf(ex_s[0], ex_s[1]);
        float e = __expf(pil_s[t] - m);
        red[t] = e;
        float ss = e;
        #pragma unroll
        for (int s = 16; s; s >>= 1) ss += __shfl_xor_sync(0xffffffffu, ss, s);
        if ((t & 31) == 0) ex_s[(t >> 5) + 2] = ss;
    }
    __syncthreads();
    if (t < 64) g_logpi[t] = __logf(red[t] / (ex_s[2] + ex_s[3]) + 1e-9f);

    // B matrix [72][128], tf32-rounded
    for (int idx = t; idx < NB * 128; idx += 1024) {
        int n = idx >> 7, k = idx & 127;
        int d = k & 63, isq = k >> 6;
        float val = 0.f;
        if (n < Kk) {
            float lvc = fminf(fmaxf(q_logvar[n * Dd + d], -5.0f), 5.0f);
            float a   = phi_s[d] * __expf(-lvc);
            float mu  = q_mu[n * Dd + d];
            if (isq) {
                val = a;
                obuf[n * Dd + d] = phi_s[d] * (LOG2PI_F + lvc) + mu * mu * a;
            } else {
                val = -2.0f * mu * a;
            }
            val = tf32r(val);
        } else if (n == Kk && isq) {
            val = tf32r((1.0f - phi_s[d]) * __expf(-PLV0));  // background column
        }
        g_Bmat[idx] = val;
    }
    __syncthreads();
    // offs: 256 threads, 4 partials per k, shfl-free smem reduce
    if (t < 256) {
        int k = t & 63, part = t >> 6;
        float s = 0.f;
        #pragma unroll
        for (int d = part * 16; d < part * 16 + 16; d++) s += obuf[k * Dd + d];
        red[0] = red[0];   // no-op keep
        obuf[part * 64 + k] = s;   // reuse obuf front as 4x64 partials
    }
    __syncthreads();
    if (t < 64)
        g_offs[t] = -0.5f * (obuf[t] + obuf[64 + t] + obuf[128 + t] + obuf[192 + t]);
}

// ---------------------------------------------------------------------------
// Kernel 2: fused main pass with mma.sync tf32 tensor cores + last-block
// finalize (loss written by the 2048th block to finish; no 3rd launch).
// ---------------------------------------------------------------------------
#define ASTR 68
#define BSTR 132
#define OFF_A    0
#define OFF_B    34816
#define OFF_OFFS 72832
#define OFF_LPI  73088
#define SMEM_BYTES 73344

__global__ void __launch_bounds__(TPB)
main_kernel(const float* __restrict__ X, float* __restrict__ out)
{
    extern __shared__ char smem[];
    float* A_s    = (float*)(smem + OFF_A);     // 128 x 68 (k=0..63 used)
    float* B_s    = (float*)(smem + OFF_B);     // 72 x 132
    float* offs_s = (float*)(smem + OFF_OFFS);
    float* lpi_s  = (float*)(smem + OFF_LPI);
    __shared__ double wsum[TPB / 32];

    const int tid = threadIdx.x, wid = tid >> 5, lane = tid & 31;
    const int g = lane >> 2, t4 = lane & 3;
    const int n0 = blockIdx.x * TM;

    // stage B (72x128 -> stride 132) via float4
    #pragma unroll
    for (int it = 0; it < 9; it++) {
        int i4 = tid + TPB * it;   // 2304 float4s
        int n = i4 >> 5, kq = (i4 & 31) << 2;
        float4 v = *(const float4*)(g_Bmat + n * 128 + kq);
        *(float4*)(B_s + n * BSTR + kq) = v;
    }
    if (tid < 64) { offs_s[tid] = g_offs[tid]; lpi_s[tid] = g_logpi[tid]; }

    // stage X tile (128x64), tf32-rounded
    #pragma unroll
    for (int it = 0; it < 8; it++) {
        int i4 = tid + TPB * it;   // 2048 float4s
        int m = i4 >> 4, kq = (i4 & 15) << 2;
        float4 v = *(const float4*)(X + (size_t)(n0 + m) * Dd + kq);
        v.x = tf32r(v.x); v.y = tf32r(v.y); v.z = tf32r(v.z); v.w = tf32r(v.w);
        *(float4*)(A_s + m * ASTR + kq) = v;
    }
    __syncthreads();

    float c[9][4];
    #pragma unroll
    for (int j = 0; j < 9; j++)
        { c[j][0] = 0.f; c[j][1] = 0.f; c[j][2] = 0.f; c[j][3] = 0.f; }

    const float* aptr = A_s + (16 * wid + g) * ASTR + t4;

    #pragma unroll
    for (int k0 = 0; k0 < 64; k0 += 8) {
        float fa0 = aptr[k0];
        float fa1 = aptr[8 * ASTR + k0];
        float fa2 = aptr[k0 + 4];
        float fa3 = aptr[8 * ASTR + k0 + 4];
        uint32_t a0 = __float_as_uint(fa0), a1 = __float_as_uint(fa1);
        uint32_t a2 = __float_as_uint(fa2), a3 = __float_as_uint(fa3);
        uint32_t q0 = __float_as_uint(tf32r(fa0 * fa0));
        uint32_t q1 = __float_as_uint(tf32r(fa1 * fa1));
        uint32_t q2 = __float_as_uint(tf32r(fa2 * fa2));
        uint32_t q3 = __float_as_uint(tf32r(fa3 * fa3));
        #pragma unroll
        for (int j = 0; j < 9; j++) {
            const float* bb = B_s + (8 * j + g) * BSTR + t4;
            uint32_t b0 = __float_as_uint(bb[k0]);
            uint32_t b1 = __float_as_uint(bb[k0 + 4]);
            mma8(c[j], a0, a1, a2, a3, b0, b1);
            uint32_t e0 = __float_as_uint(bb[k0 + 64]);
            uint32_t e1 = __float_as_uint(bb[k0 + 68]);
            mma8(c[j], q0, q1, q2, q3, e0, e1);
        }
    }

    // ---------------- epilogue ----------------
    const float C0 = g_C0;
    double lsesum = 0.0;
    #pragma unroll
    for (int h = 0; h < 2; h++) {
        int r = 16 * wid + g + 8 * h;                  // local row
        float bgq  = __shfl_sync(0xffffffffu, c[8][2 * h], lane & ~3);
        float lpbg = -0.5f * (C0 + bgq);
        float lp[16];
        float mx = -3.4e38f;
        #pragma unroll
        for (int j = 0; j < 8; j++) {
            int col = 8 * j + 2 * t4;
            float v0 = fmaf(-0.5f, c[j][2 * h],     offs_s[col])     + lpbg;
            float v1 = fmaf(-0.5f, c[j][2 * h + 1], offs_s[col + 1]) + lpbg;
            lp[2 * j] = v0; lp[2 * j + 1] = v1;
            mx = fmaxf(mx, fmaxf(v0 + lpi_s[col], v1 + lpi_s[col + 1]));
        }
        mx = fmaxf(mx, __shfl_xor_sync(0xffffffffu, mx, 1));
        mx = fmaxf(mx, __shfl_xor_sync(0xffffffffu, mx, 2));
        float se = 0.f;
        #pragma unroll
        for (int j = 0; j < 8; j++) {
            int col = 8 * j + 2 * t4;
            se += __expf(lp[2 * j]     + lpi_s[col]     - mx);
            se += __expf(lp[2 * j + 1] + lpi_s[col + 1] - mx);
        }
        se += __shfl_xor_sync(0xffffffffu, se, 1);
        se += __shfl_xor_sync(0xffffffffu, se, 2);
        if (t4 == 0) lsesum += (double)(mx + __logf(se));
        // stage lp into this warp's own A rows (each warp only ever read its
        // own 16 A rows, and is done with them)
        float* srow = A_s + r * ASTR + 2 * t4;
        #pragma unroll
        for (int j = 0; j < 8; j++)
            *(float2*)(srow + 8 * j) = make_float2(lp[2 * j], lp[2 * j + 1]);
    }

    // block-level lse reduce -> ONE atomic per block
    #pragma unroll
    for (int s = 16; s; s >>= 1)
        lsesum += __shfl_xor_sync(0xffffffffu, lsesum, s);
    if (lane == 0) wsum[wid] = lsesum;

    __syncthreads();
    // coalesced copy of staged lp (out+65 is 4B-aligned only -> scalar)
    float* obase = out + 65 + (size_t)n0 * Kk;
    #pragma unroll
    for (int i = 0; i < 32; i++) {
        int idx = tid + TPB * i;                       // 8192 floats
        obase[idx] = A_s[(idx >> 6) * ASTR + (idx & 63)];
    }

    // last-block finalize: write loss, reset accumulators for next replay
    if (tid == 0) {
        double bsum = 0.0;
        #pragma unroll
        for (int w = 0; w < TPB / 32; w++) bsum += wsum[w];
        atomicAdd(&g_lse, bsum);
        __threadfence();
        unsigned int old = atomicAdd(&g_count, 1u);
        if (old == NTILES - 1) {
            double total = atomicAdd(&g_lse, 0.0);     // all adds visible
            out[0] = (float)(g_kl - total);
            g_lse = 0.0;                                // deterministic replay
            g_count = 0u;
        }
    }
}

// ---------------------------------------------------------------------------
extern "C" void kernel_launch(void* const* d_in, const int* in_sizes, int n_in,
                              void* d_out, int out_size)
{
    const float* X  = (const float*)d_in[0];
    const float* u  = (const float*)d_in[1];
    const float* pl = (const float*)d_in[2];
    const float* mu = (const float*)d_in[3];
    const float* lv = (const float*)d_in[4];
    const float* pi = (const float*)d_in[5];
    const float* pp = (const float*)d_in[6];
    float* out = (float*)d_out;

    cudaFuncSetAttribute(main_kernel,
                         cudaFuncAttributeMaxDynamicSharedMemorySize, SMEM_BYTES);

    precompute_kernel<<<1, 1024>>>(u, pl, mu, lv, pi, pp, out);
    main_kernel<<<NTILES, TPB, SMEM_BYTES>>>(X, out);
}